// round 15
// baseline (speedup 1.0000x reference)
#include <cuda_runtime.h>
#include <cuda_fp16.h>

#define SEQ 320
#define NSCAN 720
#define NTOK (NSCAN * SEQ)

// ---------------------------------------------------------------------------
// helpers
// ---------------------------------------------------------------------------
__device__ __forceinline__ float frcp(float x) {
    float y; asm("rcp.approx.f32 %0, %1;" : "=f"(y) : "f"(x)); return y;
}
__device__ __forceinline__ unsigned pkh2(float lo, float hi) {
    unsigned d; asm("cvt.rn.f16x2.f32 %0, %1, %2;" : "=r"(d) : "f"(hi), "f"(lo)); return d;
}
__device__ __forceinline__ unsigned ex2h2(unsigned x) {
    unsigned y; asm("ex2.approx.f16x2 %0, %1;" : "=r"(y) : "r"(x)); return y;
}
__device__ __forceinline__ unsigned hadd2(unsigned a, unsigned b) {
    unsigned d; asm("add.rn.f16x2 %0, %1, %2;" : "=r"(d) : "r"(a), "r"(b)); return d;
}
__device__ __forceinline__ float2 up2(unsigned v) {
    float a, b;
    asm("{.reg .f16 l, h;\n\t mov.b32 {l, h}, %2;\n\t"
        "cvt.f32.f16 %0, l;\n\t cvt.f32.f16 %1, h;}\n"
        : "=f"(a), "=f"(b) : "r"(v));
    return make_float2(a, b);
}
__device__ __forceinline__ void mma16(float* c, unsigned a0, unsigned a1, unsigned a2,
                                      unsigned a3, unsigned b0, unsigned b1) {
    asm volatile(
        "mma.sync.aligned.m16n8k16.row.col.f32.f16.f16.f32 "
        "{%0,%1,%2,%3},{%4,%5,%6,%7},{%8,%9},{%0,%1,%2,%3};\n"
        : "+f"(c[0]), "+f"(c[1]), "+f"(c[2]), "+f"(c[3])
        : "r"(a0), "r"(a1), "r"(a2), "r"(a3), "r"(b0), "r"(b1));
}
__device__ __forceinline__ void ldsm4(unsigned& r0, unsigned& r1, unsigned& r2,
                                      unsigned& r3, const unsigned* p) {
    unsigned a = (unsigned)__cvta_generic_to_shared(p);
    asm volatile("ldmatrix.sync.aligned.m8n8.x4.shared.b16 {%0,%1,%2,%3}, [%4];"
                 : "=r"(r0), "=r"(r1), "=r"(r2), "=r"(r3) : "r"(a));
}
__device__ __forceinline__ void ldsm4t(unsigned& r0, unsigned& r1, unsigned& r2,
                                       unsigned& r3, const unsigned* p) {
    unsigned a = (unsigned)__cvta_generic_to_shared(p);
    asm volatile("ldmatrix.sync.aligned.m8n8.x4.trans.shared.b16 {%0,%1,%2,%3}, [%4];"
                 : "=r"(r0), "=r"(r1), "=r"(r2), "=r"(r3) : "r"(a));
}

#define SQLS 0.42466090f   /* sqrt(0.125*log2(e)), folded into q */

// smem layout (32-bit word offsets)
#define W_OFF   0                     /* weights; dead after ph2 -> ph3 scratch */
#define B_OFF   9216
#define QL_OFF  9728
#define QR_OFF  (9728 + 11520)
#define VL_OFF  (9728 + 2*11520)
#define VR_OFF  (9728 + 3*11520)
#define SMEM_WORDS (9728 + 4*11520)
#define SMEM_BYTES (SMEM_WORDS * 4)   /* 223232 B */

// ---------------------------------------------------------------------------
__global__ void __launch_bounds__(512, 1) fused_kernel(
    const float* __restrict__ x_l, const float* __restrict__ x_r,
    const float* __restrict__ ln_l_s, const float* __restrict__ ln_l_b,
    const float* __restrict__ ln_r_s, const float* __restrict__ ln_r_b,
    const float* __restrict__ w_ql, const float* __restrict__ b_ql,
    const float* __restrict__ w_qr, const float* __restrict__ b_qr,
    const float* __restrict__ w_vl, const float* __restrict__ b_vl,
    const float* __restrict__ w_vr, const float* __restrict__ b_vr,
    const float* __restrict__ beta, const float* __restrict__ gamma,
    float* __restrict__ out)
{
    extern __shared__ unsigned smu[];
    const int tid  = threadIdx.x;
    const int scan = blockIdx.x;

    // ---- phase 0: weights (transposed, f16x2-packed) + biases + LN params ----
    for (int i = tid; i < 8192; i += 512) {
        const int mat = i >> 11, j = i & 2047;
        const int k2 = j >> 6, n = j & 63;
        const float* wsrc = (mat == 0) ? w_ql : (mat == 1) ? w_vl : (mat == 2) ? w_qr : w_vr;
        smu[W_OFF + mat*2304 + n*36 + k2] = pkh2(wsrc[(2*k2)*64 + n], wsrc[(2*k2+1)*64 + n]);
    }
    {
        const int which = tid >> 6, c = tid & 63;
        const float* vsrc = (which == 0) ? b_ql  : (which == 1) ? b_vl  :
                            (which == 2) ? b_qr  : (which == 3) ? b_vr  :
                            (which == 4) ? ln_l_s : (which == 5) ? ln_l_b :
                            (which == 6) ? ln_r_s : ln_r_b;
        ((float*)smu)[B_OFF + tid] = vsrc[c];
    }
    __syncthreads();

    // ---- phase 1: LayerNorm + f16 staging, 4 threads per token (5 iters flat) ----
    for (int t4i = tid; t4i < 2560; t4i += 512) {
        const int t = t4i >> 2, h = t4i & 3;
        const int side = (t >= 320) ? 1 : 0;
        const int tok  = t - side * 320;
        const float* xsrc = (side ? x_r : x_l) + ((size_t)scan * 320 + tok) * 64 + h * 16;
        const float4* lns4 = (const float4*)((const float*)smu + B_OFF + 256 + side*128) + h*4;
        const float4* lnb4 = lns4 + 16;

        float4 xv[4];
#pragma unroll
        for (int i = 0; i < 4; ++i) xv[i] = ((const float4*)xsrc)[i];
        float s = 0.f;
#pragma unroll
        for (int i = 0; i < 4; ++i) s += xv[i].x + xv[i].y + xv[i].z + xv[i].w;
        s += __shfl_xor_sync(0xffffffffu, s, 1);
        s += __shfl_xor_sync(0xffffffffu, s, 2);
        const float mu = s * (1.f/64.f);
        float vs = 0.f;
#pragma unroll
        for (int i = 0; i < 4; ++i) {
            float a = xv[i].x - mu, b = xv[i].y - mu, c = xv[i].z - mu, d = xv[i].w - mu;
            vs += a*a + b*b + c*c + d*d;
        }
        vs += __shfl_xor_sync(0xffffffffu, vs, 1);
        vs += __shfl_xor_sync(0xffffffffu, vs, 2);
        const float rstd = rsqrtf(vs * (1.f/64.f) + 1e-6f);

        unsigned* qrow = smu + (side ? QR_OFF : QL_OFF) + tok * 36 + h * 8;
        unsigned* vrow = smu + (side ? VR_OFF : VL_OFF) + tok * 36 + h * 8;
#pragma unroll
        for (int i = 0; i < 4; ++i) {
            const float4 s4 = lns4[i];
            const float4 b4 = lnb4[i];
            qrow[2*i]     = pkh2((xv[i].x - mu)*rstd*s4.x + b4.x,
                                 (xv[i].y - mu)*rstd*s4.y + b4.y);
            qrow[2*i + 1] = pkh2((xv[i].z - mu)*rstd*s4.z + b4.z,
                                 (xv[i].w - mu)*rstd*s4.w + b4.w);
            vrow[2*i]     = pkh2(xv[i].x, xv[i].y);
            vrow[2*i + 1] = pkh2(xv[i].z, xv[i].w);
        }
    }
    __syncthreads();

    const int w = tid >> 5, lane = tid & 31;
    const int g = lane >> 2, t4 = lane & 3;
    // ldsm A-fragment per-lane offset: row = lane&15, k-half = lane>>4 (16B)
    const int offA = (lane & 15) * 36 + ((lane >> 4) & 1) * 4;

    // ---- phase 2a: tasks 0..31, two full tasks per warp ----
    for (int task = w; task < 32; task += 16) {
        const int side = (task >= 20) ? 1 : 0;
        const int m0 = (task - side * 20) * 16;
        const unsigned* Xn = smu + (side ? QR_OFF : QL_OFF);
        const unsigned* Xr = smu + (side ? VR_OFF : VL_OFF);
        const unsigned* Wq = smu + W_OFF + side * 4608;
        const unsigned* Wv = Wq + 2304;

        unsigned aqF[4][4], arF[4][4];
#pragma unroll
        for (int kk = 0; kk < 4; ++kk) {
            ldsm4(aqF[kk][0], aqF[kk][1], aqF[kk][2], aqF[kk][3], Xn + m0*36 + kk*8 + offA);
            ldsm4(arF[kk][0], arF[kk][1], arF[kk][2], arF[kk][3], Xr + m0*36 + kk*8 + offA);
        }

        float cQ[8][4], cV[8][4];
#pragma unroll
        for (int n = 0; n < 8; ++n)
#pragma unroll
            for (int i = 0; i < 4; ++i) { cQ[n][i] = 0.f; cV[n][i] = 0.f; }

#pragma unroll
        for (int kk = 0; kk < 4; ++kk) {
#pragma unroll
            for (int n = 0; n < 8; ++n) {
                const int bi = (8*n + g) * 36 + 8*kk + t4;
                mma16(cQ[n], aqF[kk][0], aqF[kk][1], aqF[kk][2], aqF[kk][3], Wq[bi], Wq[bi + 4]);
                mma16(cV[n], arF[kk][0], arF[kk][1], arF[kk][2], arF[kk][3], Wv[bi], Wv[bi + 4]);
            }
        }

        const float* bqp = (const float*)smu + B_OFF + side * 128;
        const float* bvp = bqp + 64;
        unsigned* qdst = smu + (side ? QR_OFF : QL_OFF);
        unsigned* vdst = smu + (side ? VR_OFF : VL_OFF);
#pragma unroll
        for (int n = 0; n < 8; ++n) {
            const int ch = 8*n + 2*t4;
            const float2 b2 = *(const float2*)(bqp + ch);
            const float2 v2 = *(const float2*)(bvp + ch);
            qdst[(m0 + g)     * 36 + 4*n + t4] = pkh2((cQ[n][0] + b2.x) * SQLS,
                                                      (cQ[n][1] + b2.y) * SQLS);
            qdst[(m0 + g + 8) * 36 + 4*n + t4] = pkh2((cQ[n][2] + b2.x) * SQLS,
                                                      (cQ[n][3] + b2.y) * SQLS);
            vdst[(m0 + g)     * 36 + 4*n + t4] = pkh2(cV[n][0] + v2.x, cV[n][1] + v2.y);
            vdst[(m0 + g + 8) * 36 + 4*n + t4] = pkh2(cV[n][2] + v2.x, cV[n][3] + v2.y);
        }
    }

    // ---- phase 2b: leftover tasks 32..39, split by output-n half across pair ----
    {
        const int p = w & 7;
        const int m0 = (12 + p) * 16;
        const int nlo = (w < 8) ? 0 : 4;
        const unsigned* Xn = smu + QR_OFF;
        const unsigned* Xr = smu + VR_OFF;
        const unsigned* Wq = smu + W_OFF + 4608;
        const unsigned* Wv = Wq + 2304;

        unsigned aqF[4][4], arF[4][4];
#pragma unroll
        for (int kk = 0; kk < 4; ++kk) {
            ldsm4(aqF[kk][0], aqF[kk][1], aqF[kk][2], aqF[kk][3], Xn + m0*36 + kk*8 + offA);
            ldsm4(arF[kk][0], arF[kk][1], arF[kk][2], arF[kk][3], Xr + m0*36 + kk*8 + offA);
        }

        float cQ[4][4], cV[4][4];
#pragma unroll
        for (int n = 0; n < 4; ++n)
#pragma unroll
            for (int i = 0; i < 4; ++i) { cQ[n][i] = 0.f; cV[n][i] = 0.f; }

#pragma unroll
        for (int kk = 0; kk < 4; ++kk) {
#pragma unroll
            for (int nn = 0; nn < 4; ++nn) {
                const int bi = (8*(nlo + nn) + g) * 36 + 8*kk + t4;
                mma16(cQ[nn], aqF[kk][0], aqF[kk][1], aqF[kk][2], aqF[kk][3], Wq[bi], Wq[bi + 4]);
                mma16(cV[nn], arF[kk][0], arF[kk][1], arF[kk][2], arF[kk][3], Wv[bi], Wv[bi + 4]);
            }
        }
        __syncthreads();   // all pair A-reads complete before in-place writes

        const float* bqp = (const float*)smu + B_OFF + 128;
        const float* bvp = bqp + 64;
        unsigned* qdst = smu + QR_OFF;
        unsigned* vdst = smu + VR_OFF;
#pragma unroll
        for (int nn = 0; nn < 4; ++nn) {
            const int n = nlo + nn;
            const int ch = 8*n + 2*t4;
            const float2 b2 = *(const float2*)(bqp + ch);
            const float2 v2 = *(const float2*)(bvp + ch);
            qdst[(m0 + g)     * 36 + 4*n + t4] = pkh2((cQ[nn][0] + b2.x) * SQLS,
                                                      (cQ[nn][1] + b2.y) * SQLS);
            qdst[(m0 + g + 8) * 36 + 4*n + t4] = pkh2((cQ[nn][2] + b2.x) * SQLS,
                                                      (cQ[nn][3] + b2.y) * SQLS);
            vdst[(m0 + g)     * 36 + 4*n + t4] = pkh2(cV[nn][0] + v2.x, cV[nn][1] + v2.y);
            vdst[(m0 + g + 8) * 36 + 4*n + t4] = pkh2(cV[nn][2] + v2.x, cV[nn][3] + v2.y);
        }
    }
    __syncthreads();

    // ---- phase 3: attention ----
    const int offK  = (lane & 7) * 36 + ((lane >> 3) & 1) * 4   + ((lane >> 4) & 1) * 288;
    const int offVt = (lane & 7) * 36 + ((lane >> 3) & 1) * 288 + ((lane >> 4) & 1) * 4;
    float* scratch = (float*)smu;   // weights region, dead after phase 2

    // ---- 3a: two full tasks per warp (tasks 0..31) ----
    for (int task = w; task < 32; task += 16) {
        const int dir = (task >= 20) ? 1 : 0;
        const int m0 = (task - dir * 20) * 16;
        const unsigned* Qs = smu + (dir ? QR_OFF : QL_OFF);
        const unsigned* Ks = smu + (dir ? QL_OFF : QR_OFF);
        const unsigned* Vs = smu + (dir ? VL_OFF : VR_OFF);
        const float* xg  = (dir ? x_r : x_l) + (size_t)scan * SEQ * 64;
        const float* svg = dir ? gamma : beta;
        float* og = out + (size_t)dir * NTOK * 64 + (size_t)scan * SEQ * 64;

        unsigned aq[4][4];
#pragma unroll
        for (int kk = 0; kk < 4; ++kk)
            ldsm4(aq[kk][0], aq[kk][1], aq[kk][2], aq[kk][3], Qs + m0*36 + kk*8 + offA);

        float o[8][4];
#pragma unroll
        for (int n = 0; n < 8; ++n) { o[n][0]=0.f; o[n][1]=0.f; o[n][2]=0.f; o[n][3]=0.f; }
        float sA = 0.f, sB = 0.f;

#pragma unroll
        for (int ch = 0; ch < 5; ++ch) {
            float c[8][4];
#pragma unroll
            for (int j = 0; j < 8; ++j) { c[j][0]=0.f; c[j][1]=0.f; c[j][2]=0.f; c[j][3]=0.f; }
#pragma unroll
            for (int kk = 0; kk < 4; ++kk) {
#pragma unroll
                for (int jp = 0; jp < 4; ++jp) {
                    unsigned b0, b1, b2, b3;
                    ldsm4(b0, b1, b2, b3, Ks + ch*2304 + jp*576 + kk*8 + offK);
                    mma16(c[2*jp],   aq[kk][0], aq[kk][1], aq[kk][2], aq[kk][3], b0, b1);
                    mma16(c[2*jp+1], aq[kk][0], aq[kk][1], aq[kk][2], aq[kk][3], b2, b3);
                }
            }
            unsigned pA[8], pB[8];
            unsigned accA = 0u, accB = 0u;
#pragma unroll
            for (int j = 0; j < 8; ++j) {
                pA[j] = ex2h2(pkh2(c[j][0], c[j][1]));
                pB[j] = ex2h2(pkh2(c[j][2], c[j][3]));
                accA = hadd2(accA, pA[j]);
                accB = hadd2(accB, pB[j]);
            }
            const float2 ua = up2(accA), ub = up2(accB);
            sA += ua.x + ua.y;
            sB += ub.x + ub.y;
#pragma unroll
            for (int kk2 = 0; kk2 < 4; ++kk2) {
                const unsigned a0 = pA[2*kk2],     a1 = pB[2*kk2];
                const unsigned a2 = pA[2*kk2 + 1], a3 = pB[2*kk2 + 1];
                const unsigned* vp = Vs + (ch*64 + kk2*16) * 36 + offVt;
#pragma unroll
                for (int np = 0; np < 4; ++np) {
                    unsigned w0, w1, w2, w3;
                    ldsm4t(w0, w1, w2, w3, vp + np*8);
                    mma16(o[2*np],   a0, a1, a2, a3, w0, w1);
                    mma16(o[2*np+1], a0, a1, a2, a3, w2, w3);
                }
            }
        }

        sA += __shfl_xor_sync(0xffffffffu, sA, 1);
        sA += __shfl_xor_sync(0xffffffffu, sA, 2);
        sB += __shfl_xor_sync(0xffffffffu, sB, 1);
        sB += __shfl_xor_sync(0xffffffffu, sB, 2);
        const float iA = frcp(sA), iB = frcp(sB);

        float* sc = scratch + w * 544;
#pragma unroll
        for (int n = 0; n < 8; ++n)
            *(float2*)(sc + g*68 + 8*n + 2*t4) = make_float2(o[n][0]*iA, o[n][1]*iA);
        __syncwarp();
#pragma unroll
        for (int i = 0; i < 4; ++i) {
            const int seg = i*128 + lane*4;
            const int row = seg >> 6, chn = seg & 63;
            const float4 ov = *(const float4*)(sc + row*68 + chn);
            const float4 xv = *(const float4*)(xg + (size_t)(m0 + row) * 64 + chn);
            const float4 sv = *(const float4*)(svg + chn);
            float4 r;
            r.x = fmaf(ov.x, sv.x, xv.x); r.y = fmaf(ov.y, sv.y, xv.y);
            r.z = fmaf(ov.z, sv.z, xv.z); r.w = fmaf(ov.w, sv.w, xv.w);
            *(float4*)(og + (size_t)(m0 + row) * 64 + chn) = r;
        }
        __syncwarp();
#pragma unroll
        for (int n = 0; n < 8; ++n)
            *(float2*)(sc + g*68 + 8*n + 2*t4) = make_float2(o[n][2]*iB, o[n][3]*iB);
        __syncwarp();
#pragma unroll
        for (int i = 0; i < 4; ++i) {
            const int seg = i*128 + lane*4;
            const int row = seg >> 6, chn = seg & 63;
            const float4 ov = *(const float4*)(sc + row*68 + chn);
            const float4 xv = *(const float4*)(xg + (size_t)(m0 + 8 + row) * 64 + chn);
            const float4 sv = *(const float4*)(svg + chn);
            float4 r;
            r.x = fmaf(ov.x, sv.x, xv.x); r.y = fmaf(ov.y, sv.y, xv.y);
            r.z = fmaf(ov.z, sv.z, xv.z); r.w = fmaf(ov.w, sv.w, xv.w);
            *(float4*)(og + (size_t)(m0 + 8 + row) * 64 + chn) = r;
        }
        __syncwarp();
    }
    __syncthreads();   // scratch region now free for partials

    // ---- 3b: half-tasks, symmetric exchange (dir 1, tiles 12..19) ----
    {
        const int p = w & 7;
        const bool isLow = (w < 8);
        const int m0 = (12 + p) * 16;
        const unsigned* Qs = smu + QR_OFF;
        const unsigned* Ks = smu + QL_OFF;
        const unsigned* Vs = smu + VL_OFF;
        const float* xg  = x_r + (size_t)scan * SEQ * 64;
        const float* svg = gamma;
        float* og = out + (size_t)NTOK * 64 + (size_t)scan * SEQ * 64;
        float* pr = scratch + p * 1152;
        float* mySub = pr + (isLow ? 0 : 576);
        float* otSub = pr + (isLow ? 576 : 0);

        unsigned aq[4][4];
#pragma unroll
        for (int kk = 0; kk < 4; ++kk)
            ldsm4(aq[kk][0], aq[kk][1], aq[kk][2], aq[kk][3], Qs + m0*36 + kk*8 + offA);

        float o[8][4];
#pragma unroll
        for (int n = 0; n < 8; ++n) { o[n][0]=0.f; o[n][1]=0.f; o[n][2]=0.f; o[n][3]=0.f; }
        float sA = 0.f, sB = 0.f;
        const int cb = isLow ? 0 : 3, ce = isLow ? 3 : 5;

#pragma unroll
        for (int ch = 0; ch < 5; ++ch) {
            if (ch < cb || ch >= ce) continue;   // warp-uniform
            float c[8][4];
#pragma unroll
            for (int j = 0; j < 8; ++j) { c[j][0]=0.f; c[j][1]=0.f; c[j][2]=0.f; c[j][3]=0.f; }
#pragma unroll
            for (int kk = 0; kk < 4; ++kk) {
#pragma unroll
                for (int jp = 0; jp < 4; ++jp) {
                    unsigned b0, b1, b2, b3;
                    ldsm4(b0, b1, b2, b3, Ks + ch*2304 + jp*576 + kk*8 + offK);
                    mma16(c[2*jp],   aq[kk][0], aq[kk][1], aq[kk][2], aq[kk][3], b0, b1);
                    mma16(c[2*jp+1], aq[kk][0], aq[kk][1], aq[kk][2], aq[kk][3], b2, b3);
                }
            }
            unsigned pA[8], pB[8];
            unsigned accA = 0u, accB = 0u;
#pragma unroll
            for (int j = 0; j < 8; ++j) {
                pA[j] = ex2h2(pkh2(c[j][0], c[j][1]));
                pB[j] = ex2h2(pkh2(c[j][2], c[j][3]));
                accA = hadd2(accA, pA[j]);
                accB = hadd2(accB, pB[j]);
            }
            const float2 ua = up2(accA), ub = up2(accB);
            sA += ua.x + ua.y;
            sB += ub.x + ub.y;
#pragma unroll
            for (int kk2 = 0; kk2 < 4; ++kk2) {
                const unsigned a0 = pA[2*kk2],     a1 = pB[2*kk2];
                const unsigned a2 = pA[2*kk2 + 1], a3 = pB[2*kk2 + 1];
                const unsigned* vp = Vs + (ch*64 + kk2*16) * 36 + offVt;
#pragma unroll
                for (int np = 0; np < 4; ++np) {
                    unsigned w0, w1, w2, w3;
                    ldsm4t(w0, w1, w2, w3, vp + np*8);
                    mma16(o[2*np],   a0, a1, a2, a3, w0, w1);
                    mma16(o[2*np+1], a0, a1, a2, a3, w2, w3);
                }
            }
        }

        // ship the half this warp does NOT finalize
        if (isLow) {
#pragma unroll
            for (int n = 0; n < 8; ++n) {
                mySub[(2*n)   * 32 + lane] = o[n][2];
                mySub[(2*n+1) * 32 + lane] = o[n][3];
            }
            mySub[512 + lane] = sB;
        } else {
#pragma unroll
            for (int n = 0; n < 8; ++n) {
                mySub[(2*n)   * 32 + lane] = o[n][0];
                mySub[(2*n+1) * 32 + lane] = o[n][1];
            }
            mySub[512 + lane] = sA;
        }
        __syncthreads();

        // combine the half this warp DOES finalize
        float inv;
        const int e0 = isLow ? 0 : 2;
        if (isLow) {
#pragma unroll
            for (int n = 0; n < 8; ++n) {
                o[n][0] += otSub[(2*n)   * 32 + lane];
                o[n][1] += otSub[(2*n+1) * 32 + lane];
            }
            float s0 = sA + otSub[512 + lane];
            s0 += __shfl_xor_sync(0xffffffffu, s0, 1);
            s0 += __shfl_xor_sync(0xffffffffu, s0, 2);
            inv = frcp(s0);
        } else {
#pragma unroll
            for (int n = 0; n < 8; ++n) {
                o[n][2] += otSub[(2*n)   * 32 + lane];
                o[n][3] += otSub[(2*n+1) * 32 + lane];
            }
            float s1 = sB + otSub[512 + lane];
            s1 += __shfl_xor_sync(0xffffffffu, s1, 1);
            s1 += __shfl_xor_sync(0xffffffffu, s1, 2);
            inv = frcp(s1);
        }
        __syncthreads();   // all exchange reads done before staging overwrites

        // each warp stages & writes its own 8 rows
        float* sc = mySub;
        const int rbase = m0 + (isLow ? 0 : 8);
#pragma unroll
        for (int n = 0; n < 8; ++n)
            *(float2*)(sc + g*68 + 8*n + 2*t4) = make_float2(o[n][e0]*inv, o[n][e0+1]*inv);
        __syncwarp();
#pragma unroll
        for (int i = 0; i < 4; ++i) {
            const int seg = i*128 + lane*4;
            const int row = seg >> 6, chn = seg & 63;
            const float4 ov = *(const float4*)(sc + row*68 + chn);
            const float4 xv = *(const float4*)(xg + (size_t)(rbase + row) * 64 + chn);
            const float4 sv = *(const float4*)(svg + chn);
            float4 r;
            r.x = fmaf(ov.x, sv.x, xv.x); r.y = fmaf(ov.y, sv.y, xv.y);
            r.z = fmaf(ov.z, sv.z, xv.z); r.w = fmaf(ov.w, sv.w, xv.w);
            *(float4*)(og + (size_t)(rbase + row) * 64 + chn) = r;
        }
    }
}

// ---------------------------------------------------------------------------
extern "C" void kernel_launch(void* const* d_in, const int* in_sizes, int n_in,
                              void* d_out, int out_size)
{
    const float* x_l    = (const float*)d_in[0];
    const float* x_r    = (const float*)d_in[1];
    const float* ln_l_s = (const float*)d_in[2];
    const float* ln_l_b = (const float*)d_in[3];
    const float* ln_r_s = (const float*)d_in[4];
    const float* ln_r_b = (const float*)d_in[5];
    const float* w_ql   = (const float*)d_in[6];
    const float* b_ql   = (const float*)d_in[7];
    const float* w_qr   = (const float*)d_in[8];
    const float* b_qr   = (const float*)d_in[9];
    const float* w_vl   = (const float*)d_in[10];
    const float* b_vl   = (const float*)d_in[11];
    const float* w_vr   = (const float*)d_in[12];
    const float* b_vr   = (const float*)d_in[13];
    const float* beta   = (const float*)d_in[14];
    const float* gamma  = (const float*)d_in[15];
    float* out = (float*)d_out;

    cudaFuncSetAttribute(fused_kernel, cudaFuncAttributeMaxDynamicSharedMemorySize, SMEM_BYTES);

    fused_kernel<<<NSCAN, 512, SMEM_BYTES>>>(
        x_l, x_r, ln_l_s, ln_l_b, ln_r_s, ln_r_b,
        w_ql, b_ql, w_qr, b_qr, w_vl, b_vl, w_vr, b_vr,
        beta, gamma, out);
}

// round 16
// speedup vs baseline: 1.0027x; 1.0027x over previous
#include <cuda_runtime.h>
#include <cuda_fp16.h>

#define SEQ 320
#define NSCAN 720
#define NTOK (NSCAN * SEQ)

// ---------------------------------------------------------------------------
// helpers
// ---------------------------------------------------------------------------
__device__ __forceinline__ float frcp(float x) {
    float y; asm("rcp.approx.f32 %0, %1;" : "=f"(y) : "f"(x)); return y;
}
__device__ __forceinline__ unsigned pkh2(float lo, float hi) {
    unsigned d; asm("cvt.rn.f16x2.f32 %0, %1, %2;" : "=r"(d) : "f"(hi), "f"(lo)); return d;
}
__device__ __forceinline__ unsigned ex2h2(unsigned x) {
    unsigned y; asm("ex2.approx.f16x2 %0, %1;" : "=r"(y) : "r"(x)); return y;
}
__device__ __forceinline__ unsigned hadd2(unsigned a, unsigned b) {
    unsigned d; asm("add.rn.f16x2 %0, %1, %2;" : "=r"(d) : "r"(a), "r"(b)); return d;
}
__device__ __forceinline__ float2 up2(unsigned v) {
    float a, b;
    asm("{.reg .f16 l, h;\n\t mov.b32 {l, h}, %2;\n\t"
        "cvt.f32.f16 %0, l;\n\t cvt.f32.f16 %1, h;}\n"
        : "=f"(a), "=f"(b) : "r"(v));
    return make_float2(a, b);
}
// f32-accumulator mma (projections + GEMM2)
__device__ __forceinline__ void mma16(float* c, unsigned a0, unsigned a1, unsigned a2,
                                      unsigned a3, unsigned b0, unsigned b1) {
    asm volatile(
        "mma.sync.aligned.m16n8k16.row.col.f32.f16.f16.f32 "
        "{%0,%1,%2,%3},{%4,%5,%6,%7},{%8,%9},{%0,%1,%2,%3};\n"
        : "+f"(c[0]), "+f"(c[1]), "+f"(c[2]), "+f"(c[3])
        : "r"(a0), "r"(a1), "r"(a2), "r"(a3), "r"(b0), "r"(b1));
}
// f16-accumulator mma (GEMM1 scores): D/C = 2 packed f16x2 regs,
// d[0] = row g, cols (2t4, 2t4+1); d[1] = row g+8 — directly ex2h2-able.
__device__ __forceinline__ void mma16h(unsigned* c, unsigned a0, unsigned a1, unsigned a2,
                                       unsigned a3, unsigned b0, unsigned b1) {
    asm volatile(
        "mma.sync.aligned.m16n8k16.row.col.f16.f16.f16.f16 "
        "{%0,%1},{%2,%3,%4,%5},{%6,%7},{%0,%1};\n"
        : "+r"(c[0]), "+r"(c[1])
        : "r"(a0), "r"(a1), "r"(a2), "r"(a3), "r"(b0), "r"(b1));
}
__device__ __forceinline__ void ldsm4(unsigned& r0, unsigned& r1, unsigned& r2,
                                      unsigned& r3, const unsigned* p) {
    unsigned a = (unsigned)__cvta_generic_to_shared(p);
    asm volatile("ldmatrix.sync.aligned.m8n8.x4.shared.b16 {%0,%1,%2,%3}, [%4];"
                 : "=r"(r0), "=r"(r1), "=r"(r2), "=r"(r3) : "r"(a));
}
__device__ __forceinline__ void ldsm4t(unsigned& r0, unsigned& r1, unsigned& r2,
                                       unsigned& r3, const unsigned* p) {
    unsigned a = (unsigned)__cvta_generic_to_shared(p);
    asm volatile("ldmatrix.sync.aligned.m8n8.x4.trans.shared.b16 {%0,%1,%2,%3}, [%4];"
                 : "=r"(r0), "=r"(r1), "=r"(r2), "=r"(r3) : "r"(a));
}

#define SQLS 0.42466090f   /* sqrt(0.125*log2(e)), folded into q */

// smem layout (32-bit word offsets)
#define W_OFF   0                     /* weights; dead after ph2 -> ph3 scratch */
#define B_OFF   9216
#define QL_OFF  9728
#define QR_OFF  (9728 + 11520)
#define VL_OFF  (9728 + 2*11520)
#define VR_OFF  (9728 + 3*11520)
#define SMEM_WORDS (9728 + 4*11520)
#define SMEM_BYTES (SMEM_WORDS * 4)   /* 223232 B */

// ---------------------------------------------------------------------------
__global__ void __launch_bounds__(512, 1) fused_kernel(
    const float* __restrict__ x_l, const float* __restrict__ x_r,
    const float* __restrict__ ln_l_s, const float* __restrict__ ln_l_b,
    const float* __restrict__ ln_r_s, const float* __restrict__ ln_r_b,
    const float* __restrict__ w_ql, const float* __restrict__ b_ql,
    const float* __restrict__ w_qr, const float* __restrict__ b_qr,
    const float* __restrict__ w_vl, const float* __restrict__ b_vl,
    const float* __restrict__ w_vr, const float* __restrict__ b_vr,
    const float* __restrict__ beta, const float* __restrict__ gamma,
    float* __restrict__ out)
{
    extern __shared__ unsigned smu[];
    const int tid  = threadIdx.x;
    const int scan = blockIdx.x;

    // ---- phase 0: weights (transposed, f16x2-packed) + biases + LN params ----
    for (int i = tid; i < 8192; i += 512) {
        const int mat = i >> 11, j = i & 2047;
        const int k2 = j >> 6, n = j & 63;
        const float* wsrc = (mat == 0) ? w_ql : (mat == 1) ? w_vl : (mat == 2) ? w_qr : w_vr;
        smu[W_OFF + mat*2304 + n*36 + k2] = pkh2(wsrc[(2*k2)*64 + n], wsrc[(2*k2+1)*64 + n]);
    }
    {
        const int which = tid >> 6, c = tid & 63;
        const float* vsrc = (which == 0) ? b_ql  : (which == 1) ? b_vl  :
                            (which == 2) ? b_qr  : (which == 3) ? b_vr  :
                            (which == 4) ? ln_l_s : (which == 5) ? ln_l_b :
                            (which == 6) ? ln_r_s : ln_r_b;
        ((float*)smu)[B_OFF + tid] = vsrc[c];
    }
    __syncthreads();

    // ---- phase 1: LayerNorm + f16 staging, 4 threads per token (5 iters flat) ----
    for (int t4i = tid; t4i < 2560; t4i += 512) {
        const int t = t4i >> 2, h = t4i & 3;
        const int side = (t >= 320) ? 1 : 0;
        const int tok  = t - side * 320;
        const float* xsrc = (side ? x_r : x_l) + ((size_t)scan * 320 + tok) * 64 + h * 16;
        const float4* lns4 = (const float4*)((const float*)smu + B_OFF + 256 + side*128) + h*4;
        const float4* lnb4 = lns4 + 16;

        float4 xv[4];
#pragma unroll
        for (int i = 0; i < 4; ++i) xv[i] = ((const float4*)xsrc)[i];
        float s = 0.f;
#pragma unroll
        for (int i = 0; i < 4; ++i) s += xv[i].x + xv[i].y + xv[i].z + xv[i].w;
        s += __shfl_xor_sync(0xffffffffu, s, 1);
        s += __shfl_xor_sync(0xffffffffu, s, 2);
        const float mu = s * (1.f/64.f);
        float vs = 0.f;
#pragma unroll
        for (int i = 0; i < 4; ++i) {
            float a = xv[i].x - mu, b = xv[i].y - mu, c = xv[i].z - mu, d = xv[i].w - mu;
            vs += a*a + b*b + c*c + d*d;
        }
        vs += __shfl_xor_sync(0xffffffffu, vs, 1);
        vs += __shfl_xor_sync(0xffffffffu, vs, 2);
        const float rstd = rsqrtf(vs * (1.f/64.f) + 1e-6f);

        unsigned* qrow = smu + (side ? QR_OFF : QL_OFF) + tok * 36 + h * 8;
        unsigned* vrow = smu + (side ? VR_OFF : VL_OFF) + tok * 36 + h * 8;
#pragma unroll
        for (int i = 0; i < 4; ++i) {
            const float4 s4 = lns4[i];
            const float4 b4 = lnb4[i];
            qrow[2*i]     = pkh2((xv[i].x - mu)*rstd*s4.x + b4.x,
                                 (xv[i].y - mu)*rstd*s4.y + b4.y);
            qrow[2*i + 1] = pkh2((xv[i].z - mu)*rstd*s4.z + b4.z,
                                 (xv[i].w - mu)*rstd*s4.w + b4.w);
            vrow[2*i]     = pkh2(xv[i].x, xv[i].y);
            vrow[2*i + 1] = pkh2(xv[i].z, xv[i].w);
        }
    }
    __syncthreads();

    const int w = tid >> 5, lane = tid & 31;
    const int g = lane >> 2, t4 = lane & 3;
    // ldsm A-fragment per-lane offset: row = lane&15, k-half = lane>>4 (16B)
    const int offA = (lane & 15) * 36 + ((lane >> 4) & 1) * 4;

    // ---- phase 2a: tasks 0..31, two full tasks per warp ----
    for (int task = w; task < 32; task += 16) {
        const int side = (task >= 20) ? 1 : 0;
        const int m0 = (task - side * 20) * 16;
        const unsigned* Xn = smu + (side ? QR_OFF : QL_OFF);
        const unsigned* Xr = smu + (side ? VR_OFF : VL_OFF);
        const unsigned* Wq = smu + W_OFF + side * 4608;
        const unsigned* Wv = Wq + 2304;

        unsigned aqF[4][4], arF[4][4];
#pragma unroll
        for (int kk = 0; kk < 4; ++kk) {
            ldsm4(aqF[kk][0], aqF[kk][1], aqF[kk][2], aqF[kk][3], Xn + m0*36 + kk*8 + offA);
            ldsm4(arF[kk][0], arF[kk][1], arF[kk][2], arF[kk][3], Xr + m0*36 + kk*8 + offA);
        }

        float cQ[8][4], cV[8][4];
#pragma unroll
        for (int n = 0; n < 8; ++n)
#pragma unroll
            for (int i = 0; i < 4; ++i) { cQ[n][i] = 0.f; cV[n][i] = 0.f; }

#pragma unroll
        for (int kk = 0; kk < 4; ++kk) {
#pragma unroll
            for (int n = 0; n < 8; ++n) {
                const int bi = (8*n + g) * 36 + 8*kk + t4;
                mma16(cQ[n], aqF[kk][0], aqF[kk][1], aqF[kk][2], aqF[kk][3], Wq[bi], Wq[bi + 4]);
                mma16(cV[n], arF[kk][0], arF[kk][1], arF[kk][2], arF[kk][3], Wv[bi], Wv[bi + 4]);
            }
        }

        const float* bqp = (const float*)smu + B_OFF + side * 128;
        const float* bvp = bqp + 64;
        unsigned* qdst = smu + (side ? QR_OFF : QL_OFF);
        unsigned* vdst = smu + (side ? VR_OFF : VL_OFF);
#pragma unroll
        for (int n = 0; n < 8; ++n) {
            const int ch = 8*n + 2*t4;
            const float2 b2 = *(const float2*)(bqp + ch);
            const float2 v2 = *(const float2*)(bvp + ch);
            qdst[(m0 + g)     * 36 + 4*n + t4] = pkh2((cQ[n][0] + b2.x) * SQLS,
                                                      (cQ[n][1] + b2.y) * SQLS);
            qdst[(m0 + g + 8) * 36 + 4*n + t4] = pkh2((cQ[n][2] + b2.x) * SQLS,
                                                      (cQ[n][3] + b2.y) * SQLS);
            vdst[(m0 + g)     * 36 + 4*n + t4] = pkh2(cV[n][0] + v2.x, cV[n][1] + v2.y);
            vdst[(m0 + g + 8) * 36 + 4*n + t4] = pkh2(cV[n][2] + v2.x, cV[n][3] + v2.y);
        }
    }

    // ---- phase 2b: leftover tasks 32..39, split by output-n half across pair ----
    {
        const int p = w & 7;
        const int m0 = (12 + p) * 16;
        const int nlo = (w < 8) ? 0 : 4;
        const unsigned* Xn = smu + QR_OFF;
        const unsigned* Xr = smu + VR_OFF;
        const unsigned* Wq = smu + W_OFF + 4608;
        const unsigned* Wv = Wq + 2304;

        unsigned aqF[4][4], arF[4][4];
#pragma unroll
        for (int kk = 0; kk < 4; ++kk) {
            ldsm4(aqF[kk][0], aqF[kk][1], aqF[kk][2], aqF[kk][3], Xn + m0*36 + kk*8 + offA);
            ldsm4(arF[kk][0], arF[kk][1], arF[kk][2], arF[kk][3], Xr + m0*36 + kk*8 + offA);
        }

        float cQ[4][4], cV[4][4];
#pragma unroll
        for (int n = 0; n < 4; ++n)
#pragma unroll
            for (int i = 0; i < 4; ++i) { cQ[n][i] = 0.f; cV[n][i] = 0.f; }

#pragma unroll
        for (int kk = 0; kk < 4; ++kk) {
#pragma unroll
            for (int nn = 0; nn < 4; ++nn) {
                const int bi = (8*(nlo + nn) + g) * 36 + 8*kk + t4;
                mma16(cQ[nn], aqF[kk][0], aqF[kk][1], aqF[kk][2], aqF[kk][3], Wq[bi], Wq[bi + 4]);
                mma16(cV[nn], arF[kk][0], arF[kk][1], arF[kk][2], arF[kk][3], Wv[bi], Wv[bi + 4]);
            }
        }
        __syncthreads();   // all pair A-reads complete before in-place writes

        const float* bqp = (const float*)smu + B_OFF + 128;
        const float* bvp = bqp + 64;
        unsigned* qdst = smu + QR_OFF;
        unsigned* vdst = smu + VR_OFF;
#pragma unroll
        for (int nn = 0; nn < 4; ++nn) {
            const int n = nlo + nn;
            const int ch = 8*n + 2*t4;
            const float2 b2 = *(const float2*)(bqp + ch);
            const float2 v2 = *(const float2*)(bvp + ch);
            qdst[(m0 + g)     * 36 + 4*n + t4] = pkh2((cQ[nn][0] + b2.x) * SQLS,
                                                      (cQ[nn][1] + b2.y) * SQLS);
            qdst[(m0 + g + 8) * 36 + 4*n + t4] = pkh2((cQ[nn][2] + b2.x) * SQLS,
                                                      (cQ[nn][3] + b2.y) * SQLS);
            vdst[(m0 + g)     * 36 + 4*n + t4] = pkh2(cV[nn][0] + v2.x, cV[nn][1] + v2.y);
            vdst[(m0 + g + 8) * 36 + 4*n + t4] = pkh2(cV[nn][2] + v2.x, cV[nn][3] + v2.y);
        }
    }
    __syncthreads();

    // ---- phase 3: attention ----
    const int offK  = (lane & 7) * 36 + ((lane >> 3) & 1) * 4   + ((lane >> 4) & 1) * 288;
    const int offVt = (lane & 7) * 36 + ((lane >> 3) & 1) * 288 + ((lane >> 4) & 1) * 4;
    float* scratch = (float*)smu;   // weights region, dead after phase 2

    // ---- 3a: two full tasks per warp (tasks 0..31) ----
    for (int task = w; task < 32; task += 16) {
        const int dir = (task >= 20) ? 1 : 0;
        const int m0 = (task - dir * 20) * 16;
        const unsigned* Qs = smu + (dir ? QR_OFF : QL_OFF);
        const unsigned* Ks = smu + (dir ? QL_OFF : QR_OFF);
        const unsigned* Vs = smu + (dir ? VL_OFF : VR_OFF);
        const float* xg  = (dir ? x_r : x_l) + (size_t)scan * SEQ * 64;
        const float* svg = dir ? gamma : beta;
        float* og = out + (size_t)dir * NTOK * 64 + (size_t)scan * SEQ * 64;

        unsigned aq[4][4];
#pragma unroll
        for (int kk = 0; kk < 4; ++kk)
            ldsm4(aq[kk][0], aq[kk][1], aq[kk][2], aq[kk][3], Qs + m0*36 + kk*8 + offA);

        float o[8][4];
#pragma unroll
        for (int n = 0; n < 8; ++n) { o[n][0]=0.f; o[n][1]=0.f; o[n][2]=0.f; o[n][3]=0.f; }
        float sA = 0.f, sB = 0.f;

#pragma unroll
        for (int ch = 0; ch < 5; ++ch) {
            // GEMM1 with f16 accumulators: cc[j][0] = row g pair, cc[j][1] = row g+8 pair
            unsigned cc[8][2];
#pragma unroll
            for (int j = 0; j < 8; ++j) { cc[j][0] = 0u; cc[j][1] = 0u; }
#pragma unroll
            for (int kk = 0; kk < 4; ++kk) {
#pragma unroll
                for (int jp = 0; jp < 4; ++jp) {
                    unsigned b0, b1, b2, b3;
                    ldsm4(b0, b1, b2, b3, Ks + ch*2304 + jp*576 + kk*8 + offK);
                    mma16h(cc[2*jp],   aq[kk][0], aq[kk][1], aq[kk][2], aq[kk][3], b0, b1);
                    mma16h(cc[2*jp+1], aq[kk][0], aq[kk][1], aq[kk][2], aq[kk][3], b2, b3);
                }
            }
            // ex2 directly on packed f16x2 scores; output IS the P A-fragment
            unsigned pA[8], pB[8];
            unsigned accA = 0u, accB = 0u;
#pragma unroll
            for (int j = 0; j < 8; ++j) {
                pA[j] = ex2h2(cc[j][0]);
                pB[j] = ex2h2(cc[j][1]);
                accA = hadd2(accA, pA[j]);
                accB = hadd2(accB, pB[j]);
            }
            const float2 ua = up2(accA), ub = up2(accB);
            sA += ua.x + ua.y;
            sB += ub.x + ub.y;
#pragma unroll
            for (int kk2 = 0; kk2 < 4; ++kk2) {
                const unsigned a0 = pA[2*kk2],     a1 = pB[2*kk2];
                const unsigned a2 = pA[2*kk2 + 1], a3 = pB[2*kk2 + 1];
                const unsigned* vp = Vs + (ch*64 + kk2*16) * 36 + offVt;
#pragma unroll
                for (int np = 0; np < 4; ++np) {
                    unsigned w0, w1, w2, w3;
                    ldsm4t(w0, w1, w2, w3, vp + np*8);
                    mma16(o[2*np],   a0, a1, a2, a3, w0, w1);
                    mma16(o[2*np+1], a0, a1, a2, a3, w2, w3);
                }
            }
        }

        sA += __shfl_xor_sync(0xffffffffu, sA, 1);
        sA += __shfl_xor_sync(0xffffffffu, sA, 2);
        sB += __shfl_xor_sync(0xffffffffu, sB, 1);
        sB += __shfl_xor_sync(0xffffffffu, sB, 2);
        const float iA = frcp(sA), iB = frcp(sB);

        float* sc = scratch + w * 544;
#pragma unroll
        for (int n = 0; n < 8; ++n)
            *(float2*)(sc + g*68 + 8*n + 2*t4) = make_float2(o[n][0]*iA, o[n][1]*iA);
        __syncwarp();
#pragma unroll
        for (int i = 0; i < 4; ++i) {
            const int seg = i*128 + lane*4;
            const int row = seg >> 6, chn = seg & 63;
            const float4 ov = *(const float4*)(sc + row*68 + chn);
            const float4 xv = *(const float4*)(xg + (size_t)(m0 + row) * 64 + chn);
            const float4 sv = *(const float4*)(svg + chn);
            float4 r;
            r.x = fmaf(ov.x, sv.x, xv.x); r.y = fmaf(ov.y, sv.y, xv.y);
            r.z = fmaf(ov.z, sv.z, xv.z); r.w = fmaf(ov.w, sv.w, xv.w);
            *(float4*)(og + (size_t)(m0 + row) * 64 + chn) = r;
        }
        __syncwarp();
#pragma unroll
        for (int n = 0; n < 8; ++n)
            *(float2*)(sc + g*68 + 8*n + 2*t4) = make_float2(o[n][2]*iB, o[n][3]*iB);
        __syncwarp();
#pragma unroll
        for (int i = 0; i < 4; ++i) {
            const int seg = i*128 + lane*4;
            const int row = seg >> 6, chn = seg & 63;
            const float4 ov = *(const float4*)(sc + row*68 + chn);
            const float4 xv = *(const float4*)(xg + (size_t)(m0 + 8 + row) * 64 + chn);
            const float4 sv = *(const float4*)(svg + chn);
            float4 r;
            r.x = fmaf(ov.x, sv.x, xv.x); r.y = fmaf(ov.y, sv.y, xv.y);
            r.z = fmaf(ov.z, sv.z, xv.z); r.w = fmaf(ov.w, sv.w, xv.w);
            *(float4*)(og + (size_t)(m0 + 8 + row) * 64 + chn) = r;
        }
        __syncwarp();
    }
    __syncthreads();   // scratch region now free for partials

    // ---- 3b: half-tasks, symmetric exchange (dir 1, tiles 12..19) ----
    {
        const int p = w & 7;
        const bool isLow = (w < 8);
        const int m0 = (12 + p) * 16;
        const unsigned* Qs = smu + QR_OFF;
        const unsigned* Ks = smu + QL_OFF;
        const unsigned* Vs = smu + VL_OFF;
        const float* xg  = x_r + (size_t)scan * SEQ * 64;
        const float* svg = gamma;
        float* og = out + (size_t)NTOK * 64 + (size_t)scan * SEQ * 64;
        float* pr = scratch + p * 1152;
        float* mySub = pr + (isLow ? 0 : 576);
        float* otSub = pr + (isLow ? 576 : 0);

        unsigned aq[4][4];
#pragma unroll
        for (int kk = 0; kk < 4; ++kk)
            ldsm4(aq[kk][0], aq[kk][1], aq[kk][2], aq[kk][3], Qs + m0*36 + kk*8 + offA);

        float o[8][4];
#pragma unroll
        for (int n = 0; n < 8; ++n) { o[n][0]=0.f; o[n][1]=0.f; o[n][2]=0.f; o[n][3]=0.f; }
        float sA = 0.f, sB = 0.f;
        const int cb = isLow ? 0 : 3, ce = isLow ? 3 : 5;

#pragma unroll
        for (int ch = 0; ch < 5; ++ch) {
            if (ch < cb || ch >= ce) continue;   // warp-uniform
            unsigned cc[8][2];
#pragma unroll
            for (int j = 0; j < 8; ++j) { cc[j][0] = 0u; cc[j][1] = 0u; }
#pragma unroll
            for (int kk = 0; kk < 4; ++kk) {
#pragma unroll
                for (int jp = 0; jp < 4; ++jp) {
                    unsigned b0, b1, b2, b3;
                    ldsm4(b0, b1, b2, b3, Ks + ch*2304 + jp*576 + kk*8 + offK);
                    mma16h(cc[2*jp],   aq[kk][0], aq[kk][1], aq[kk][2], aq[kk][3], b0, b1);
                    mma16h(cc[2*jp+1], aq[kk][0], aq[kk][1], aq[kk][2], aq[kk][3], b2, b3);
                }
            }
            unsigned pA[8], pB[8];
            unsigned accA = 0u, accB = 0u;
#pragma unroll
            for (int j = 0; j < 8; ++j) {
                pA[j] = ex2h2(cc[j][0]);
                pB[j] = ex2h2(cc[j][1]);
                accA = hadd2(accA, pA[j]);
                accB = hadd2(accB, pB[j]);
            }
            const float2 ua = up2(accA), ub = up2(accB);
            sA += ua.x + ua.y;
            sB += ub.x + ub.y;
#pragma unroll
            for (int kk2 = 0; kk2 < 4; ++kk2) {
                const unsigned a0 = pA[2*kk2],     a1 = pB[2*kk2];
                const unsigned a2 = pA[2*kk2 + 1], a3 = pB[2*kk2 + 1];
                const unsigned* vp = Vs + (ch*64 + kk2*16) * 36 + offVt;
#pragma unroll
                for (int np = 0; np < 4; ++np) {
                    unsigned w0, w1, w2, w3;
                    ldsm4t(w0, w1, w2, w3, vp + np*8);
                    mma16(o[2*np],   a0, a1, a2, a3, w0, w1);
                    mma16(o[2*np+1], a0, a1, a2, a3, w2, w3);
                }
            }
        }

        // ship the half this warp does NOT finalize
        if (isLow) {
#pragma unroll
            for (int n = 0; n < 8; ++n) {
                mySub[(2*n)   * 32 + lane] = o[n][2];
                mySub[(2*n+1) * 32 + lane] = o[n][3];
            }
            mySub[512 + lane] = sB;
        } else {
#pragma unroll
            for (int n = 0; n < 8; ++n) {
                mySub[(2*n)   * 32 + lane] = o[n][0];
                mySub[(2*n+1) * 32 + lane] = o[n][1];
            }
            mySub[512 + lane] = sA;
        }
        __syncthreads();

        // combine the half this warp DOES finalize
        float inv;
        const int e0 = isLow ? 0 : 2;
        if (isLow) {
#pragma unroll
            for (int n = 0; n < 8; ++n) {
                o[n][0] += otSub[(2*n)   * 32 + lane];
                o[n][1] += otSub[(2*n+1) * 32 + lane];
            }
            float s0 = sA + otSub[512 + lane];
            s0 += __shfl_xor_sync(0xffffffffu, s0, 1);
            s0 += __shfl_xor_sync(0xffffffffu, s0, 2);
            inv = frcp(s0);
        } else {
#pragma unroll
            for (int n = 0; n < 8; ++n) {
                o[n][2] += otSub[(2*n)   * 32 + lane];
                o[n][3] += otSub[(2*n+1) * 32 + lane];
            }
            float s1 = sB + otSub[512 + lane];
            s1 += __shfl_xor_sync(0xffffffffu, s1, 1);
            s1 += __shfl_xor_sync(0xffffffffu, s1, 2);
            inv = frcp(s1);
        }
        __syncthreads();   // all exchange reads done before staging overwrites

        // each warp stages & writes its own 8 rows
        float* sc = mySub;
        const int rbase = m0 + (isLow ? 0 : 8);
#pragma unroll
        for (int n = 0; n < 8; ++n)
            *(float2*)(sc + g*68 + 8*n + 2*t4) = make_float2(o[n][e0]*inv, o[n][e0+1]*inv);
        __syncwarp();
#pragma unroll
        for (int i = 0; i < 4; ++i) {
            const int seg = i*128 + lane*4;
            const int row = seg >> 6, chn = seg & 63;
            const float4 ov = *(const float4*)(sc + row*68 + chn);
            const float4 xv = *(const float4*)(xg + (size_t)(rbase + row) * 64 + chn);
            const float4 sv = *(const float4*)(svg + chn);
            float4 r;
            r.x = fmaf(ov.x, sv.x, xv.x); r.y = fmaf(ov.y, sv.y, xv.y);
            r.z = fmaf(ov.z, sv.z, xv.z); r.w = fmaf(ov.w, sv.w, xv.w);
            *(float4*)(og + (size_t)(rbase + row) * 64 + chn) = r;
        }
    }
}

// ---------------------------------------------------------------------------
extern "C" void kernel_launch(void* const* d_in, const int* in_sizes, int n_in,
                              void* d_out, int out_size)
{
    const float* x_l    = (const float*)d_in[0];
    const float* x_r    = (const float*)d_in[1];
    const float* ln_l_s = (const float*)d_in[2];
    const float* ln_l_b = (const float*)d_in[3];
    const float* ln_r_s = (const float*)d_in[4];
    const float* ln_r_b = (const float*)d_in[5];
    const float* w_ql   = (const float*)d_in[6];
    const float* b_ql   = (const float*)d_in[7];
    const float* w_qr   = (const float*)d_in[8];
    const float* b_qr   = (const float*)d_in[9];
    const float* w_vl   = (const float*)d_in[10];
    const float* b_vl   = (const float*)d_in[11];
    const float* w_vr   = (const float*)d_in[12];
    const float* b_vr   = (const float*)d_in[13];
    const float* beta   = (const float*)d_in[14];
    const float* gamma  = (const float*)d_in[15];
    float* out = (float*)d_out;

    cudaFuncSetAttribute(fused_kernel, cudaFuncAttributeMaxDynamicSharedMemorySize, SMEM_BYTES);

    fused_kernel<<<NSCAN, 512, SMEM_BYTES>>>(
        x_l, x_r, ln_l_s, ln_l_b, ln_r_s, ln_r_b,
        w_ql, b_ql, w_qr, b_qr, w_vl, b_vl, w_vr, b_vr,
        beta, gamma, out);
}

// round 17
// speedup vs baseline: 1.0143x; 1.0116x over previous
#include <cuda_runtime.h>
#include <cuda_fp16.h>

#define SEQ 320
#define NSCAN 720
#define NTOK (NSCAN * SEQ)

// ---------------------------------------------------------------------------
// helpers
// ---------------------------------------------------------------------------
__device__ __forceinline__ float frcp(float x) {
    float y; asm("rcp.approx.f32 %0, %1;" : "=f"(y) : "f"(x)); return y;
}
__device__ __forceinline__ unsigned pkh2(float lo, float hi) {
    unsigned d; asm("cvt.rn.f16x2.f32 %0, %1, %2;" : "=r"(d) : "f"(hi), "f"(lo)); return d;
}
__device__ __forceinline__ unsigned ex2h2(unsigned x) {
    unsigned y; asm("ex2.approx.f16x2 %0, %1;" : "=r"(y) : "r"(x)); return y;
}
__device__ __forceinline__ unsigned hadd2(unsigned a, unsigned b) {
    unsigned d; asm("add.rn.f16x2 %0, %1, %2;" : "=r"(d) : "r"(a), "r"(b)); return d;
}
__device__ __forceinline__ float2 up2(unsigned v) {
    float a, b;
    asm("{.reg .f16 l, h;\n\t mov.b32 {l, h}, %2;\n\t"
        "cvt.f32.f16 %0, l;\n\t cvt.f32.f16 %1, h;}\n"
        : "=f"(a), "=f"(b) : "r"(v));
    return make_float2(a, b);
}
// f32-accumulator mma (projections + GEMM2)
__device__ __forceinline__ void mma16(float* c, unsigned a0, unsigned a1, unsigned a2,
                                      unsigned a3, unsigned b0, unsigned b1) {
    asm volatile(
        "mma.sync.aligned.m16n8k16.row.col.f32.f16.f16.f32 "
        "{%0,%1,%2,%3},{%4,%5,%6,%7},{%8,%9},{%0,%1,%2,%3};\n"
        : "+f"(c[0]), "+f"(c[1]), "+f"(c[2]), "+f"(c[3])
        : "r"(a0), "r"(a1), "r"(a2), "r"(a3), "r"(b0), "r"(b1));
}
// f16-accumulator mma (GEMM1 scores): D/C = 2 packed f16x2 regs
__device__ __forceinline__ void mma16h(unsigned* c, unsigned a0, unsigned a1, unsigned a2,
                                       unsigned a3, unsigned b0, unsigned b1) {
    asm volatile(
        "mma.sync.aligned.m16n8k16.row.col.f16.f16.f16.f16 "
        "{%0,%1},{%2,%3,%4,%5},{%6,%7},{%0,%1};\n"
        : "+r"(c[0]), "+r"(c[1])
        : "r"(a0), "r"(a1), "r"(a2), "r"(a3), "r"(b0), "r"(b1));
}
__device__ __forceinline__ void ldsm4(unsigned& r0, unsigned& r1, unsigned& r2,
                                      unsigned& r3, const unsigned* p) {
    unsigned a = (unsigned)__cvta_generic_to_shared(p);
    asm volatile("ldmatrix.sync.aligned.m8n8.x4.shared.b16 {%0,%1,%2,%3}, [%4];"
                 : "=r"(r0), "=r"(r1), "=r"(r2), "=r"(r3) : "r"(a));
}
__device__ __forceinline__ void ldsm4t(unsigned& r0, unsigned& r1, unsigned& r2,
                                       unsigned& r3, const unsigned* p) {
    unsigned a = (unsigned)__cvta_generic_to_shared(p);
    asm volatile("ldmatrix.sync.aligned.m8n8.x4.trans.shared.b16 {%0,%1,%2,%3}, [%4];"
                 : "=r"(r0), "=r"(r1), "=r"(r2), "=r"(r3) : "r"(a));
}

#define SQLS 0.42466090f   /* sqrt(0.125*log2(e)), folded into q */

// smem layout (32-bit word offsets)
#define W_OFF   0                     /* weights; dead after ph2 -> ph3 scratch */
#define B_OFF   9216
#define QL_OFF  9728
#define QR_OFF  (9728 + 11520)
#define VL_OFF  (9728 + 2*11520)
#define VR_OFF  (9728 + 3*11520)
#define SMEM_WORDS (9728 + 4*11520)
#define SMEM_BYTES (SMEM_WORDS * 4)   /* 223232 B */

// ---------------------------------------------------------------------------
// one 16-key attention group: GEMM1 -> ex2 -> rowsum -> GEMM2 (short chains,
// groups are mutually independent -> ptxas can software-pipeline them)
// ---------------------------------------------------------------------------
__device__ __forceinline__ void attn_group(
    const unsigned* __restrict__ Ks, const unsigned* __restrict__ Vs,
    int gj, int offK, int offVt, const unsigned aq[4][4],
    float o[8][4], float& sA, float& sB)
{
    unsigned cc0[2] = {0u, 0u}, cc1[2] = {0u, 0u};
#pragma unroll
    for (int kk = 0; kk < 4; ++kk) {
        unsigned b0, b1, b2, b3;
        ldsm4(b0, b1, b2, b3, Ks + gj*576 + kk*8 + offK);
        mma16h(cc0, aq[kk][0], aq[kk][1], aq[kk][2], aq[kk][3], b0, b1);
        mma16h(cc1, aq[kk][0], aq[kk][1], aq[kk][2], aq[kk][3], b2, b3);
    }
    const unsigned a0 = ex2h2(cc0[0]);   // row g,   keys gj*16+0..7
    const unsigned a1 = ex2h2(cc0[1]);   // row g+8, keys gj*16+0..7
    const unsigned a2 = ex2h2(cc1[0]);   // row g,   keys gj*16+8..15
    const unsigned a3 = ex2h2(cc1[1]);   // row g+8, keys gj*16+8..15
    const float2 ua = up2(hadd2(a0, a2));
    const float2 ub = up2(hadd2(a1, a3));
    sA += ua.x + ua.y;
    sB += ub.x + ub.y;
    const unsigned* vp = Vs + gj*576 + offVt;
#pragma unroll
    for (int np = 0; np < 4; ++np) {
        unsigned w0, w1, w2, w3;
        ldsm4t(w0, w1, w2, w3, vp + np*8);
        mma16(o[2*np],   a0, a1, a2, a3, w0, w1);
        mma16(o[2*np+1], a0, a1, a2, a3, w2, w3);
    }
}

// ---------------------------------------------------------------------------
__global__ void __launch_bounds__(512, 1) fused_kernel(
    const float* __restrict__ x_l, const float* __restrict__ x_r,
    const float* __restrict__ ln_l_s, const float* __restrict__ ln_l_b,
    const float* __restrict__ ln_r_s, const float* __restrict__ ln_r_b,
    const float* __restrict__ w_ql, const float* __restrict__ b_ql,
    const float* __restrict__ w_qr, const float* __restrict__ b_qr,
    const float* __restrict__ w_vl, const float* __restrict__ b_vl,
    const float* __restrict__ w_vr, const float* __restrict__ b_vr,
    const float* __restrict__ beta, const float* __restrict__ gamma,
    float* __restrict__ out)
{
    extern __shared__ unsigned smu[];
    const int tid  = threadIdx.x;
    const int scan = blockIdx.x;

    // ---- phase 0: weights (transposed, f16x2-packed) + biases + LN params ----
    for (int i = tid; i < 8192; i += 512) {
        const int mat = i >> 11, j = i & 2047;
        const int k2 = j >> 6, n = j & 63;
        const float* wsrc = (mat == 0) ? w_ql : (mat == 1) ? w_vl : (mat == 2) ? w_qr : w_vr;
        smu[W_OFF + mat*2304 + n*36 + k2] = pkh2(wsrc[(2*k2)*64 + n], wsrc[(2*k2+1)*64 + n]);
    }
    {
        const int which = tid >> 6, c = tid & 63;
        const float* vsrc = (which == 0) ? b_ql  : (which == 1) ? b_vl  :
                            (which == 2) ? b_qr  : (which == 3) ? b_vr  :
                            (which == 4) ? ln_l_s : (which == 5) ? ln_l_b :
                            (which == 6) ? ln_r_s : ln_r_b;
        ((float*)smu)[B_OFF + tid] = vsrc[c];
    }
    __syncthreads();

    // ---- phase 1: LayerNorm + f16 staging, 4 threads per token ----
    for (int t4i = tid; t4i < 2560; t4i += 512) {
        const int t = t4i >> 2, h = t4i & 3;
        const int side = (t >= 320) ? 1 : 0;
        const int tok  = t - side * 320;
        const float* xsrc = (side ? x_r : x_l) + ((size_t)scan * 320 + tok) * 64 + h * 16;
        const float4* lns4 = (const float4*)((const float*)smu + B_OFF + 256 + side*128) + h*4;
        const float4* lnb4 = lns4 + 16;

        float4 xv[4];
#pragma unroll
        for (int i = 0; i < 4; ++i) xv[i] = ((const float4*)xsrc)[i];
        float s = 0.f;
#pragma unroll
        for (int i = 0; i < 4; ++i) s += xv[i].x + xv[i].y + xv[i].z + xv[i].w;
        s += __shfl_xor_sync(0xffffffffu, s, 1);
        s += __shfl_xor_sync(0xffffffffu, s, 2);
        const float mu = s * (1.f/64.f);
        float vs = 0.f;
#pragma unroll
        for (int i = 0; i < 4; ++i) {
            float a = xv[i].x - mu, b = xv[i].y - mu, c = xv[i].z - mu, d = xv[i].w - mu;
            vs += a*a + b*b + c*c + d*d;
        }
        vs += __shfl_xor_sync(0xffffffffu, vs, 1);
        vs += __shfl_xor_sync(0xffffffffu, vs, 2);
        const float rstd = rsqrtf(vs * (1.f/64.f) + 1e-6f);

        unsigned* qrow = smu + (side ? QR_OFF : QL_OFF) + tok * 36 + h * 8;
        unsigned* vrow = smu + (side ? VR_OFF : VL_OFF) + tok * 36 + h * 8;
#pragma unroll
        for (int i = 0; i < 4; ++i) {
            const float4 s4 = lns4[i];
            const float4 b4 = lnb4[i];
            qrow[2*i]     = pkh2((xv[i].x - mu)*rstd*s4.x + b4.x,
                                 (xv[i].y - mu)*rstd*s4.y + b4.y);
            qrow[2*i + 1] = pkh2((xv[i].z - mu)*rstd*s4.z + b4.z,
                                 (xv[i].w - mu)*rstd*s4.w + b4.w);
            vrow[2*i]     = pkh2(xv[i].x, xv[i].y);
            vrow[2*i + 1] = pkh2(xv[i].z, xv[i].w);
        }
    }
    __syncthreads();

    const int w = tid >> 5, lane = tid & 31;
    const int g = lane >> 2, t4 = lane & 3;
    const int offA = (lane & 15) * 36 + ((lane >> 4) & 1) * 4;

    // ---- phase 2a: tasks 0..31, two full tasks per warp ----
    for (int task = w; task < 32; task += 16) {
        const int side = (task >= 20) ? 1 : 0;
        const int m0 = (task - side * 20) * 16;
        const unsigned* Xn = smu + (side ? QR_OFF : QL_OFF);
        const unsigned* Xr = smu + (side ? VR_OFF : VL_OFF);
        const unsigned* Wq = smu + W_OFF + side * 4608;
        const unsigned* Wv = Wq + 2304;

        unsigned aqF[4][4], arF[4][4];
#pragma unroll
        for (int kk = 0; kk < 4; ++kk) {
            ldsm4(aqF[kk][0], aqF[kk][1], aqF[kk][2], aqF[kk][3], Xn + m0*36 + kk*8 + offA);
            ldsm4(arF[kk][0], arF[kk][1], arF[kk][2], arF[kk][3], Xr + m0*36 + kk*8 + offA);
        }

        float cQ[8][4], cV[8][4];
#pragma unroll
        for (int n = 0; n < 8; ++n)
#pragma unroll
            for (int i = 0; i < 4; ++i) { cQ[n][i] = 0.f; cV[n][i] = 0.f; }

#pragma unroll
        for (int kk = 0; kk < 4; ++kk) {
#pragma unroll
            for (int n = 0; n < 8; ++n) {
                const int bi = (8*n + g) * 36 + 8*kk + t4;
                mma16(cQ[n], aqF[kk][0], aqF[kk][1], aqF[kk][2], aqF[kk][3], Wq[bi], Wq[bi + 4]);
                mma16(cV[n], arF[kk][0], arF[kk][1], arF[kk][2], arF[kk][3], Wv[bi], Wv[bi + 4]);
            }
        }

        const float* bqp = (const float*)smu + B_OFF + side * 128;
        const float* bvp = bqp + 64;
        unsigned* qdst = smu + (side ? QR_OFF : QL_OFF);
        unsigned* vdst = smu + (side ? VR_OFF : VL_OFF);
#pragma unroll
        for (int n = 0; n < 8; ++n) {
            const int ch = 8*n + 2*t4;
            const float2 b2 = *(const float2*)(bqp + ch);
            const float2 v2 = *(const float2*)(bvp + ch);
            qdst[(m0 + g)     * 36 + 4*n + t4] = pkh2((cQ[n][0] + b2.x) * SQLS,
                                                      (cQ[n][1] + b2.y) * SQLS);
            qdst[(m0 + g + 8) * 36 + 4*n + t4] = pkh2((cQ[n][2] + b2.x) * SQLS,
                                                      (cQ[n][3] + b2.y) * SQLS);
            vdst[(m0 + g)     * 36 + 4*n + t4] = pkh2(cV[n][0] + v2.x, cV[n][1] + v2.y);
            vdst[(m0 + g + 8) * 36 + 4*n + t4] = pkh2(cV[n][2] + v2.x, cV[n][3] + v2.y);
        }
    }

    // ---- phase 2b: leftover tasks 32..39, split by output-n half across pair ----
    {
        const int p = w & 7;
        const int m0 = (12 + p) * 16;
        const int nlo = (w < 8) ? 0 : 4;
        const unsigned* Xn = smu + QR_OFF;
        const unsigned* Xr = smu + VR_OFF;
        const unsigned* Wq = smu + W_OFF + 4608;
        const unsigned* Wv = Wq + 2304;

        unsigned aqF[4][4], arF[4][4];
#pragma unroll
        for (int kk = 0; kk < 4; ++kk) {
            ldsm4(aqF[kk][0], aqF[kk][1], aqF[kk][2], aqF[kk][3], Xn + m0*36 + kk*8 + offA);
            ldsm4(arF[kk][0], arF[kk][1], arF[kk][2], arF[kk][3], Xr + m0*36 + kk*8 + offA);
        }

        float cQ[4][4], cV[4][4];
#pragma unroll
        for (int n = 0; n < 4; ++n)
#pragma unroll
            for (int i = 0; i < 4; ++i) { cQ[n][i] = 0.f; cV[n][i] = 0.f; }

#pragma unroll
        for (int kk = 0; kk < 4; ++kk) {
#pragma unroll
            for (int nn = 0; nn < 4; ++nn) {
                const int bi = (8*(nlo + nn) + g) * 36 + 8*kk + t4;
                mma16(cQ[nn], aqF[kk][0], aqF[kk][1], aqF[kk][2], aqF[kk][3], Wq[bi], Wq[bi + 4]);
                mma16(cV[nn], arF[kk][0], arF[kk][1], arF[kk][2], arF[kk][3], Wv[bi], Wv[bi + 4]);
            }
        }
        __syncthreads();   // all pair A-reads complete before in-place writes

        const float* bqp = (const float*)smu + B_OFF + 128;
        const float* bvp = bqp + 64;
        unsigned* qdst = smu + QR_OFF;
        unsigned* vdst = smu + VR_OFF;
#pragma unroll
        for (int nn = 0; nn < 4; ++nn) {
            const int n = nlo + nn;
            const int ch = 8*n + 2*t4;
            const float2 b2 = *(const float2*)(bqp + ch);
            const float2 v2 = *(const float2*)(bvp + ch);
            qdst[(m0 + g)     * 36 + 4*n + t4] = pkh2((cQ[nn][0] + b2.x) * SQLS,
                                                      (cQ[nn][1] + b2.y) * SQLS);
            qdst[(m0 + g + 8) * 36 + 4*n + t4] = pkh2((cQ[nn][2] + b2.x) * SQLS,
                                                      (cQ[nn][3] + b2.y) * SQLS);
            vdst[(m0 + g)     * 36 + 4*n + t4] = pkh2(cV[nn][0] + v2.x, cV[nn][1] + v2.y);
            vdst[(m0 + g + 8) * 36 + 4*n + t4] = pkh2(cV[nn][2] + v2.x, cV[nn][3] + v2.y);
        }
    }
    __syncthreads();

    // ---- phase 3: attention (16-key groups, pipelined) ----
    const int offK  = (lane & 7) * 36 + ((lane >> 3) & 1) * 4   + ((lane >> 4) & 1) * 288;
    const int offVt = (lane & 7) * 36 + ((lane >> 3) & 1) * 288 + ((lane >> 4) & 1) * 4;
    float* scratch = (float*)smu;   // weights region, dead after phase 2

    // ---- 3a: two full tasks per warp (tasks 0..31) ----
    for (int task = w; task < 32; task += 16) {
        const int dir = (task >= 20) ? 1 : 0;
        const int m0 = (task - dir * 20) * 16;
        const unsigned* Qs = smu + (dir ? QR_OFF : QL_OFF);
        const unsigned* Ks = smu + (dir ? QL_OFF : QR_OFF);
        const unsigned* Vs = smu + (dir ? VL_OFF : VR_OFF);
        const float* xg  = (dir ? x_r : x_l) + (size_t)scan * SEQ * 64;
        const float* svg = dir ? gamma : beta;
        float* og = out + (size_t)dir * NTOK * 64 + (size_t)scan * SEQ * 64;

        unsigned aq[4][4];
#pragma unroll
        for (int kk = 0; kk < 4; ++kk)
            ldsm4(aq[kk][0], aq[kk][1], aq[kk][2], aq[kk][3], Qs + m0*36 + kk*8 + offA);

        float o[8][4];
#pragma unroll
        for (int n = 0; n < 8; ++n) { o[n][0]=0.f; o[n][1]=0.f; o[n][2]=0.f; o[n][3]=0.f; }
        float sA = 0.f, sB = 0.f;

#pragma unroll 4
        for (int gj = 0; gj < 20; ++gj)
            attn_group(Ks, Vs, gj, offK, offVt, aq, o, sA, sB);

        sA += __shfl_xor_sync(0xffffffffu, sA, 1);
        sA += __shfl_xor_sync(0xffffffffu, sA, 2);
        sB += __shfl_xor_sync(0xffffffffu, sB, 1);
        sB += __shfl_xor_sync(0xffffffffu, sB, 2);
        const float iA = frcp(sA), iB = frcp(sB);

        float* sc = scratch + w * 544;
#pragma unroll
        for (int n = 0; n < 8; ++n)
            *(float2*)(sc + g*68 + 8*n + 2*t4) = make_float2(o[n][0]*iA, o[n][1]*iA);
        __syncwarp();
#pragma unroll
        for (int i = 0; i < 4; ++i) {
            const int seg = i*128 + lane*4;
            const int row = seg >> 6, chn = seg & 63;
            const float4 ov = *(const float4*)(sc + row*68 + chn);
            const float4 xv = *(const float4*)(xg + (size_t)(m0 + row) * 64 + chn);
            const float4 sv = *(const float4*)(svg + chn);
            float4 r;
            r.x = fmaf(ov.x, sv.x, xv.x); r.y = fmaf(ov.y, sv.y, xv.y);
            r.z = fmaf(ov.z, sv.z, xv.z); r.w = fmaf(ov.w, sv.w, xv.w);
            *(float4*)(og + (size_t)(m0 + row) * 64 + chn) = r;
        }
        __syncwarp();
#pragma unroll
        for (int n = 0; n < 8; ++n)
            *(float2*)(sc + g*68 + 8*n + 2*t4) = make_float2(o[n][2]*iB, o[n][3]*iB);
        __syncwarp();
#pragma unroll
        for (int i = 0; i < 4; ++i) {
            const int seg = i*128 + lane*4;
            const int row = seg >> 6, chn = seg & 63;
            const float4 ov = *(const float4*)(sc + row*68 + chn);
            const float4 xv = *(const float4*)(xg + (size_t)(m0 + 8 + row) * 64 + chn);
            const float4 sv = *(const float4*)(svg + chn);
            float4 r;
            r.x = fmaf(ov.x, sv.x, xv.x); r.y = fmaf(ov.y, sv.y, xv.y);
            r.z = fmaf(ov.z, sv.z, xv.z); r.w = fmaf(ov.w, sv.w, xv.w);
            *(float4*)(og + (size_t)(m0 + 8 + row) * 64 + chn) = r;
        }
        __syncwarp();
    }
    __syncthreads();   // scratch region now free for partials

    // ---- 3b: half-tasks, symmetric exchange (dir 1, tiles 12..19) ----
    {
        const int p = w & 7;
        const bool isLow = (w < 8);
        const int m0 = (12 + p) * 16;
        const unsigned* Qs = smu + QR_OFF;
        const unsigned* Ks = smu + QL_OFF;
        const unsigned* Vs = smu + VL_OFF;
        const float* xg  = x_r + (size_t)scan * SEQ * 64;
        const float* svg = gamma;
        float* og = out + (size_t)NTOK * 64 + (size_t)scan * SEQ * 64;
        float* pr = scratch + p * 1152;
        float* mySub = pr + (isLow ? 0 : 576);
        float* otSub = pr + (isLow ? 576 : 0);

        unsigned aq[4][4];
#pragma unroll
        for (int kk = 0; kk < 4; ++kk)
            ldsm4(aq[kk][0], aq[kk][1], aq[kk][2], aq[kk][3], Qs + m0*36 + kk*8 + offA);

        float o[8][4];
#pragma unroll
        for (int n = 0; n < 8; ++n) { o[n][0]=0.f; o[n][1]=0.f; o[n][2]=0.f; o[n][3]=0.f; }
        float sA = 0.f, sB = 0.f;
        // low warp: key groups 0..11 (keys 0-191); high: groups 12..19
        const int gb = isLow ? 0 : 12, ge = isLow ? 12 : 20;

#pragma unroll 4
        for (int gj = gb; gj < ge; ++gj)
            attn_group(Ks, Vs, gj, offK, offVt, aq, o, sA, sB);

        // ship the half this warp does NOT finalize
        if (isLow) {
#pragma unroll
            for (int n = 0; n < 8; ++n) {
                mySub[(2*n)   * 32 + lane] = o[n][2];
                mySub[(2*n+1) * 32 + lane] = o[n][3];
            }
            mySub[512 + lane] = sB;
        } else {
#pragma unroll
            for (int n = 0; n < 8; ++n) {
                mySub[(2*n)   * 32 + lane] = o[n][0];
                mySub[(2*n+1) * 32 + lane] = o[n][1];
            }
            mySub[512 + lane] = sA;
        }
        __syncthreads();

        // combine the half this warp DOES finalize
        float inv;
        const int e0 = isLow ? 0 : 2;
        if (isLow) {
#pragma unroll
            for (int n = 0; n < 8; ++n) {
                o[n][0] += otSub[(2*n)   * 32 + lane];
                o[n][1] += otSub[(2*n+1) * 32 + lane];
            }
            float s0 = sA + otSub[512 + lane];
            s0 += __shfl_xor_sync(0xffffffffu, s0, 1);
            s0 += __shfl_xor_sync(0xffffffffu, s0, 2);
            inv = frcp(s0);
        } else {
#pragma unroll
            for (int n = 0; n < 8; ++n) {
                o[n][2] += otSub[(2*n)   * 32 + lane];
                o[n][3] += otSub[(2*n+1) * 32 + lane];
            }
            float s1 = sB + otSub[512 + lane];
            s1 += __shfl_xor_sync(0xffffffffu, s1, 1);
            s1 += __shfl_xor_sync(0xffffffffu, s1, 2);
            inv = frcp(s1);
        }
        __syncthreads();   // all exchange reads done before staging overwrites

        // each warp stages & writes its own 8 rows
        float* sc = mySub;
        const int rbase = m0 + (isLow ? 0 : 8);
#pragma unroll
        for (int n = 0; n < 8; ++n)
            *(float2*)(sc + g*68 + 8*n + 2*t4) = make_float2(o[n][e0]*inv, o[n][e0+1]*inv);
        __syncwarp();
#pragma unroll
        for (int i = 0; i < 4; ++i) {
            const int seg = i*128 + lane*4;
            const int row = seg >> 6, chn = seg & 63;
            const float4 ov = *(const float4*)(sc + row*68 + chn);
            const float4 xv = *(const float4*)(xg + (size_t)(rbase + row) * 64 + chn);
            const float4 sv = *(const float4*)(svg + chn);
            float4 r;
            r.x = fmaf(ov.x, sv.x, xv.x); r.y = fmaf(ov.y, sv.y, xv.y);
            r.z = fmaf(ov.z, sv.z, xv.z); r.w = fmaf(ov.w, sv.w, xv.w);
            *(float4*)(og + (size_t)(rbase + row) * 64 + chn) = r;
        }
    }
}

// ---------------------------------------------------------------------------
extern "C" void kernel_launch(void* const* d_in, const int* in_sizes, int n_in,
                              void* d_out, int out_size)
{
    const float* x_l    = (const float*)d_in[0];
    const float* x_r    = (const float*)d_in[1];
    const float* ln_l_s = (const float*)d_in[2];
    const float* ln_l_b = (const float*)d_in[3];
    const float* ln_r_s = (const float*)d_in[4];
    const float* ln_r_b = (const float*)d_in[5];
    const float* w_ql   = (const float*)d_in[6];
    const float* b_ql   = (const float*)d_in[7];
    const float* w_qr   = (const float*)d_in[8];
    const float* b_qr   = (const float*)d_in[9];
    const float* w_vl   = (const float*)d_in[10];
    const float* b_vl   = (const float*)d_in[11];
    const float* w_vr   = (const float*)d_in[12];
    const float* b_vr   = (const float*)d_in[13];
    const float* beta   = (const float*)d_in[14];
    const float* gamma  = (const float*)d_in[15];
    float* out = (float*)d_out;

    cudaFuncSetAttribute(fused_kernel, cudaFuncAttributeMaxDynamicSharedMemorySize, SMEM_BYTES);

    fused_kernel<<<NSCAN, 512, SMEM_BYTES>>>(
        x_l, x_r, ln_l_s, ln_l_b, ln_r_s, ln_r_b,
        w_ql, b_ql, w_qr, b_qr, w_vl, b_vl, w_vr, b_vr,
        beta, gamma, out);
}